// round 4
// baseline (speedup 1.0000x reference)
#include <cuda_runtime.h>
#include <cstdint>
#include <cmath>

// ---------------------------------------------------------------------------
// Problem constants
// ---------------------------------------------------------------------------
namespace {
constexpr int BATCH = 4, NSEQ = 2048, DIM = 1024, NH = 16, DHD = 64, INNER = 1024;
constexpr int MTOK = BATCH * NSEQ;                    // 8192
constexpr float CEXP = 0.125f * 1.4426950408889634f;  // softmax scale * log2(e)
}

// Scratch (allocation-free rule: __device__ globals)
__device__ float g_Q[MTOK * INNER];   // [B,H,N,DH]
__device__ float g_K[MTOK * INNER];   // [B,H,N,DH]
__device__ float g_V[MTOK * INNER];   // [B,H,N,DH]
__device__ float g_O[MTOK * INNER];   // [B,N,H*DH]

// ---------------------------------------------------------------------------
// tf32 helpers
// ---------------------------------------------------------------------------
__device__ __forceinline__ uint32_t f2tf(float x) {
    uint32_t u;
    asm("cvt.rna.tf32.f32 %0, %1;" : "=r"(u) : "f"(x));
    return u;
}
__device__ __forceinline__ float4 tf4(float4 v) {
    float4 w;
    w.x = __uint_as_float(f2tf(v.x));
    w.y = __uint_as_float(f2tf(v.y));
    w.z = __uint_as_float(f2tf(v.z));
    w.w = __uint_as_float(f2tf(v.w));
    return w;
}
__device__ __forceinline__ uint32_t fbits(float x) { return __float_as_uint(x); }

// D += A(16x8) * B(8x8), tf32 inputs, fp32 accum
__device__ __forceinline__ void mma_tf32(float* d, const uint32_t* a, uint32_t b0, uint32_t b1) {
    asm volatile(
        "mma.sync.aligned.m16n8k8.row.col.f32.tf32.tf32.f32 "
        "{%0,%1,%2,%3}, {%4,%5,%6,%7}, {%8,%9}, {%0,%1,%2,%3};"
        : "+f"(d[0]), "+f"(d[1]), "+f"(d[2]), "+f"(d[3])
        : "r"(a[0]), "r"(a[1]), "r"(a[2]), "r"(a[3]), "r"(b0), "r"(b1));
}

// ---------------------------------------------------------------------------
// GEMM: C[8192,1024] = X[8192,1024] @ W[1024,1024]  (tf32 MMA, 128x128x32 tiles)
// MODE 0: QKV projections (blockIdx.z selects W + headed output layout)
// MODE 1: output projection + bias -> d_out (row-major)
// ---------------------------------------------------------------------------
constexpr int BM = 128, BN = 128, BK = 32;
constexpr int ASTR = BK + 4;   // 36: conflict-free A-frag LDS
constexpr int BSTR = BN + 8;   // 136: conflict-free B-frag LDS
constexpr int GEMM_SMEM = (2 * BM * ASTR + 2 * BK * BSTR) * 4;  // 71680 B

template <int MODE>
__global__ void __launch_bounds__(256)
gemm_tf32(const float* __restrict__ X,
          const float* __restrict__ W0,
          const float* __restrict__ W1,
          const float* __restrict__ W2,
          const float* __restrict__ bias,
          float* __restrict__ outp)
{
    extern __shared__ float sm[];
    float* As = sm;
    float* Bs = sm + 2 * BM * ASTR;

    const int m0 = blockIdx.y * BM;
    const int n0 = blockIdx.x * BN;

    const float* W;
    float* out;
    if (MODE == 0) {
        if (blockIdx.z == 0)      { W = W0; out = g_Q; }
        else if (blockIdx.z == 1) { W = W1; out = g_K; }
        else                      { W = W2; out = g_V; }
    } else {
        W = W0;            // Wo
        out = outp;
        X = g_O;           // attention output scratch
    }

    const int tid  = threadIdx.x;
    const int lane = tid & 31;
    const int wid  = tid >> 5;
    const int wm   = wid >> 2;   // 0..1 (64-row warp tiles)
    const int wn   = wid & 3;    // 0..3 (32-col warp tiles)
    const int gr   = lane >> 2;
    const int q4   = lane & 3;

    float acc[4][4][4];
    #pragma unroll
    for (int i = 0; i < 4; i++)
        #pragma unroll
        for (int j = 0; j < 4; j++)
            #pragma unroll
            for (int v = 0; v < 4; v++) acc[i][j][v] = 0.f;

    // gmem load mapping (256 threads, 4 float4 each per operand)
    const int arow = tid >> 3, ac4 = tid & 7;    // A: 128 rows x 8 float4
    const int brow = tid >> 5, bc4 = tid & 31;   // B: 32 rows x 32 float4

    float4 ra[4], rb[4];

    auto load_g = [&](int k0) {
        #pragma unroll
        for (int j = 0; j < 4; j++)
            ra[j] = *(const float4*)(X + (size_t)(m0 + arow + j * 32) * 1024 + k0 + ac4 * 4);
        #pragma unroll
        for (int j = 0; j < 4; j++)
            rb[j] = *(const float4*)(W + (size_t)(k0 + brow + j * 8) * 1024 + n0 + bc4 * 4);
    };
    auto store_s = [&](int buf) {
        float* Ad = As + buf * BM * ASTR;
        float* Bd = Bs + buf * BK * BSTR;
        #pragma unroll
        for (int j = 0; j < 4; j++)
            *(float4*)(Ad + (arow + j * 32) * ASTR + ac4 * 4) = tf4(ra[j]);
        #pragma unroll
        for (int j = 0; j < 4; j++)
            *(float4*)(Bd + (brow + j * 8) * BSTR + bc4 * 4) = tf4(rb[j]);
    };

    load_g(0);
    store_s(0);
    __syncthreads();

    const int NKT = 1024 / BK;  // 32
    #pragma unroll 1
    for (int kt = 0; kt < NKT; ++kt) {
        if (kt + 1 < NKT) load_g((kt + 1) * BK);

        const float* Ac = As + (kt & 1) * BM * ASTR;
        const float* Bc = Bs + (kt & 1) * BK * BSTR;

        #pragma unroll
        for (int ks = 0; ks < 4; ++ks) {
            uint32_t af[4][4], bf[4][2];
            #pragma unroll
            for (int mi = 0; mi < 4; mi++) {
                int r = wm * 64 + mi * 16 + gr;
                int c = ks * 8 + q4;
                af[mi][0] = fbits(Ac[r * ASTR + c]);
                af[mi][1] = fbits(Ac[(r + 8) * ASTR + c]);
                af[mi][2] = fbits(Ac[r * ASTR + c + 4]);
                af[mi][3] = fbits(Ac[(r + 8) * ASTR + c + 4]);
            }
            #pragma unroll
            for (int ni = 0; ni < 4; ni++) {
                int cc = wn * 32 + ni * 8 + gr;
                int kk = ks * 8 + q4;
                bf[ni][0] = fbits(Bc[kk * BSTR + cc]);
                bf[ni][1] = fbits(Bc[(kk + 4) * BSTR + cc]);
            }
            #pragma unroll
            for (int mi = 0; mi < 4; mi++)
                #pragma unroll
                for (int ni = 0; ni < 4; ni++)
                    mma_tf32(acc[mi][ni], af[mi], bf[ni][0], bf[ni][1]);
        }

        if (kt + 1 < NKT) store_s((kt + 1) & 1);
        __syncthreads();
    }

    // Epilogue
    #pragma unroll
    for (int mi = 0; mi < 4; mi++) {
        int r = m0 + wm * 64 + mi * 16 + gr;
        #pragma unroll
        for (int ni = 0; ni < 4; ni++) {
            int c = n0 + wn * 32 + ni * 8 + 2 * q4;
            if (MODE == 0) {
                // token r -> (b, n); col c -> (h, d); write [B,H,N,DH]
                int b = r >> 11, ntk = r & (NSEQ - 1);
                int h = c >> 6, d = c & 63;
                float* p0 = out + ((size_t)((b * NH + h) * NSEQ + ntk)) * DHD + d;
                float* p1 = out + ((size_t)((b * NH + h) * NSEQ + ntk + 8)) * DHD + d;
                *(float2*)p0 = make_float2(acc[mi][ni][0], acc[mi][ni][1]);
                *(float2*)p1 = make_float2(acc[mi][ni][2], acc[mi][ni][3]);
            } else {
                float2 bv = *(const float2*)(bias + c);
                *(float2*)(out + (size_t)r * DIM + c) =
                    make_float2(acc[mi][ni][0] + bv.x, acc[mi][ni][1] + bv.y);
                *(float2*)(out + (size_t)(r + 8) * DIM + c) =
                    make_float2(acc[mi][ni][2] + bv.x, acc[mi][ni][3] + bv.y);
            }
        }
    }
}

// ---------------------------------------------------------------------------
// Flash attention: per CTA = 128 query rows of one (b,h); loop 16 key tiles
// of 128. S,O in registers; P via padded smem for re-fragmentation.
// ---------------------------------------------------------------------------
constexpr int KSTR = 68;    // Kt stride: conflict-free QK^T B-frag LDS
constexpr int VSTR = 72;    // Vt stride: conflict-free PV B-frag LDS
constexpr int PSTR = 132;   // Ps stride: conflict-free PV A-frag LDS
constexpr int FLASH_SMEM = (128 * KSTR + 128 * VSTR + 128 * PSTR) * 4;  // 139264 B

__global__ void __launch_bounds__(256)
flash_attn()
{
    extern __shared__ float sm[];
    float* Kt = sm;
    float* Vt = Kt + 128 * KSTR;
    float* Ps = Vt + 128 * VSTR;

    const int bh = blockIdx.y;            // b*H + h
    const int m0 = blockIdx.x * 128;
    const float* Qg = g_Q + ((size_t)bh * NSEQ + m0) * DHD;
    const float* Kg = g_K + (size_t)bh * NSEQ * DHD;
    const float* Vg = g_V + (size_t)bh * NSEQ * DHD;

    const int tid = threadIdx.x, lane = tid & 31, wid = tid >> 5;
    const int gr = lane >> 2, q4 = lane & 3;
    const int qrow = wid * 16 + gr;       // this thread's even query row (of its warp tile)

    const int ldrow = tid >> 4, ldc4 = tid & 15;  // tile staging: 128 rows x 16 float4

    // Stage Q (tf32) into Ps region (stride KSTR), build A-fragments, free it.
    #pragma unroll
    for (int j = 0; j < 8; j++) {
        int r = ldrow + j * 16;
        float4 v = *(const float4*)(Qg + (size_t)r * DHD + ldc4 * 4);
        *(float4*)(Ps + r * KSTR + ldc4 * 4) = tf4(v);
    }
    __syncthreads();
    uint32_t qf[8][4];
    #pragma unroll
    for (int kc = 0; kc < 8; kc++) {
        int c = kc * 8 + q4;
        qf[kc][0] = fbits(Ps[qrow * KSTR + c]);
        qf[kc][1] = fbits(Ps[(qrow + 8) * KSTR + c]);
        qf[kc][2] = fbits(Ps[qrow * KSTR + c + 4]);
        qf[kc][3] = fbits(Ps[(qrow + 8) * KSTR + c + 4]);
    }
    __syncthreads();

    float o[8][4];
    #pragma unroll
    for (int i = 0; i < 8; i++)
        #pragma unroll
        for (int v = 0; v < 4; v++) o[i][v] = 0.f;
    float mrow[2] = {-INFINITY, -INFINITY};
    float lrow[2] = {0.f, 0.f};

    for (int it = 0; it < NSEQ / 128; ++it) {
        const float* Kp = Kg + (size_t)it * 128 * DHD;
        const float* Vp = Vg + (size_t)it * 128 * DHD;
        #pragma unroll
        for (int j = 0; j < 8; j++) {
            int r = ldrow + j * 16;
            float4 kv = *(const float4*)(Kp + (size_t)r * DHD + ldc4 * 4);
            *(float4*)(Kt + r * KSTR + ldc4 * 4) = tf4(kv);
            float4 vv = *(const float4*)(Vp + (size_t)r * DHD + ldc4 * 4);
            *(float4*)(Vt + r * VSTR + ldc4 * 4) = tf4(vv);
        }
        __syncthreads();

        // S = Q @ K^T : 16 rows x 128 keys per warp
        float s[16][4];
        #pragma unroll
        for (int nt = 0; nt < 16; nt++)
            #pragma unroll
            for (int v = 0; v < 4; v++) s[nt][v] = 0.f;
        #pragma unroll
        for (int kc = 0; kc < 8; kc++) {
            #pragma unroll
            for (int nt = 0; nt < 16; nt++) {
                int n = nt * 8 + gr;
                int kk = kc * 8 + q4;
                uint32_t b0 = fbits(Kt[n * KSTR + kk]);
                uint32_t b1 = fbits(Kt[n * KSTR + kk + 4]);
                mma_tf32(s[nt], qf[kc], b0, b1);
            }
        }

        // Online softmax over the 128-key tile (rows qrow, qrow+8)
        #pragma unroll
        for (int r = 0; r < 2; r++) {
            const int i0 = 2 * r;
            float tm = -INFINITY;
            #pragma unroll
            for (int nt = 0; nt < 16; nt++)
                tm = fmaxf(tm, fmaxf(s[nt][i0], s[nt][i0 + 1]));
            tm = fmaxf(tm, __shfl_xor_sync(0xffffffffu, tm, 1));
            tm = fmaxf(tm, __shfl_xor_sync(0xffffffffu, tm, 2));
            float mnew = fmaxf(mrow[r], tm);
            float alpha = exp2f((mrow[r] - mnew) * CEXP);
            mrow[r] = mnew;
            float ps = 0.f;
            #pragma unroll
            for (int nt = 0; nt < 16; nt++) {
                float p0 = exp2f((s[nt][i0] - mnew) * CEXP);
                float p1 = exp2f((s[nt][i0 + 1] - mnew) * CEXP);
                s[nt][i0] = p0; s[nt][i0 + 1] = p1;
                ps += p0 + p1;
            }
            ps += __shfl_xor_sync(0xffffffffu, ps, 1);
            ps += __shfl_xor_sync(0xffffffffu, ps, 2);
            lrow[r] = lrow[r] * alpha + ps;
            #pragma unroll
            for (int nt = 0; nt < 8; nt++) { o[nt][i0] *= alpha; o[nt][i0 + 1] *= alpha; }
        }

        // Scatter P (tf32) into this warp's private rows of Ps
        #pragma unroll
        for (int nt = 0; nt < 16; nt++) {
            int cb = nt * 8 + 2 * q4;
            float2 p01 = make_float2(__uint_as_float(f2tf(s[nt][0])),
                                     __uint_as_float(f2tf(s[nt][1])));
            float2 p23 = make_float2(__uint_as_float(f2tf(s[nt][2])),
                                     __uint_as_float(f2tf(s[nt][3])));
            *(float2*)(Ps + qrow * PSTR + cb) = p01;
            *(float2*)(Ps + (qrow + 8) * PSTR + cb) = p23;
        }
        __syncwarp();

        // O += P @ V : keys are the K-dim (16 chunks of 8)
        #pragma unroll
        for (int kc = 0; kc < 16; kc++) {
            uint32_t a[4];
            int cc = kc * 8 + q4;
            a[0] = fbits(Ps[qrow * PSTR + cc]);
            a[1] = fbits(Ps[(qrow + 8) * PSTR + cc]);
            a[2] = fbits(Ps[qrow * PSTR + cc + 4]);
            a[3] = fbits(Ps[(qrow + 8) * PSTR + cc + 4]);
            #pragma unroll
            for (int nt = 0; nt < 8; nt++) {
                int nn = nt * 8 + gr;
                int kk = kc * 8 + q4;
                uint32_t b0 = fbits(Vt[kk * VSTR + nn]);
                uint32_t b1 = fbits(Vt[(kk + 4) * VSTR + nn]);
                mma_tf32(o[nt], a, b0, b1);
            }
        }
        __syncthreads();
    }

    // Epilogue: O /= l, write [B, N, H*DH]
    const float inv0 = 1.f / lrow[0];
    const float inv1 = 1.f / lrow[1];
    const int b = bh / NH, h = bh % NH;
    float* Og = g_O + ((size_t)(b * NSEQ + m0)) * INNER + h * DHD;
    #pragma unroll
    for (int nt = 0; nt < 8; nt++) {
        int d = nt * 8 + 2 * q4;
        *(float2*)(Og + (size_t)qrow * INNER + d) =
            make_float2(o[nt][0] * inv0, o[nt][1] * inv0);
        *(float2*)(Og + (size_t)(qrow + 8) * INNER + d) =
            make_float2(o[nt][2] * inv1, o[nt][3] * inv1);
    }
}

// ---------------------------------------------------------------------------
// Launch
// ---------------------------------------------------------------------------
extern "C" void kernel_launch(void* const* d_in, const int* in_sizes, int n_in,
                              void* d_out, int out_size) {
    (void)in_sizes; (void)n_in; (void)out_size;
    const float* x  = (const float*)d_in[0];
    const float* Wq = (const float*)d_in[1];
    const float* Wk = (const float*)d_in[2];
    const float* Wv = (const float*)d_in[3];
    const float* Wo = (const float*)d_in[4];
    const float* bo = (const float*)d_in[5];
    float* out = (float*)d_out;

    cudaFuncSetAttribute(gemm_tf32<0>, cudaFuncAttributeMaxDynamicSharedMemorySize, GEMM_SMEM);
    cudaFuncSetAttribute(gemm_tf32<1>, cudaFuncAttributeMaxDynamicSharedMemorySize, GEMM_SMEM);
    cudaFuncSetAttribute(flash_attn,   cudaFuncAttributeMaxDynamicSharedMemorySize, FLASH_SMEM);

    // 1) Q/K/V projections (z selects which)
    gemm_tf32<0><<<dim3(INNER / BN, MTOK / BM, 3), 256, GEMM_SMEM>>>(
        x, Wq, Wk, Wv, nullptr, nullptr);
    // 2) attention
    flash_attn<<<dim3(NSEQ / 128, BATCH * NH), 256, FLASH_SMEM>>>();
    // 3) output projection + bias
    gemm_tf32<1><<<dim3(DIM / BN, MTOK / BM, 1), 256, GEMM_SMEM>>>(
        nullptr, Wo, nullptr, nullptr, bo, out);
}